// round 12
// baseline (speedup 1.0000x reference)
#include <cuda_runtime.h>

// GyroLoss forward — BCH(2) log-domain with warp-segmented merges.
// One thread per 4 increments (524288 threads). Thread scans its 4 increments
// (S,C), two shuffle-merge stages build the 16-group on lane m=0, one more
// builds the level-5 pair; single converged log/huber per thread (lane m=0:
// level-4, lane m=1: level-5 routed from m=0). Last-block finalize.

#define DT_F 0.01f
#define HUBER_F 0.005f
#define NPER4 2048
#define NPER5 1024
#define N0 5
#define TPB 256

__device__ double g_sum4 = 0.0;
__device__ double g_sum5 = 0.0;
__device__ unsigned int g_count = 0u;

__device__ __forceinline__ void qmul(const float a[4], const float b[4], float c[4]) {
    c[0] = a[0]*b[0] - a[1]*b[1] - a[2]*b[2] - a[3]*b[3];
    c[1] = a[0]*b[1] + a[1]*b[0] + a[2]*b[3] - a[3]*b[2];
    c[2] = a[0]*b[2] - a[1]*b[3] + a[2]*b[0] + a[3]*b[1];
    c[3] = a[0]*b[3] + a[1]*b[2] - a[2]*b[1] + a[3]*b[0];
}

// c = conj(a) ⊗ b   (relative rotation A^T B)
__device__ __forceinline__ void qcmul(const float a[4], const float b[4], float c[4]) {
    c[0] = a[0]*b[0] + a[1]*b[1] + a[2]*b[2] + a[3]*b[3];
    c[1] = a[0]*b[1] - a[1]*b[0] - a[2]*b[3] + a[3]*b[2];
    c[2] = a[0]*b[2] + a[1]*b[3] - a[2]*b[0] - a[3]*b[1];
    c[3] = a[0]*b[3] - a[1]*b[2] + a[2]*b[1] - a[3]*b[0];
}

// exp of small phi (already-scaled) -> quaternion
__device__ __forceinline__ void qexp_phi_small(float x, float y, float z, float q[4]) {
    float sq = x*x + y*y + z*z;
    float hq = 0.25f * sq;
    q[0] = 1.0f + hq * (-0.5f + hq * (1.0f / 24.0f));
    float sf = 0.5f * (1.0f + hq * (-(1.0f / 6.0f) + hq * (1.0f / 120.0f)));
    q[1] = sf * x; q[2] = sf * y; q[3] = sf * z;
}

// full-range exp (xs path)
__device__ __forceinline__ void qexp_full(float x, float y, float z, float q[4]) {
    float sq = x*x + y*y + z*z;
    float a = sq * __frsqrt_rn(fmaxf(sq, 1e-16f));
    float h = 0.5f * a;
    float sh = __sinf(h), ch = __cosf(h);
    float sf = __fdividef(sh, fmaxf(a, 1e-8f));
    q[0] = ch; q[1] = sf * x; q[2] = sf * y; q[3] = sf * z;
}

// minimax atan on [0,1], abs err ~1e-6
__device__ __forceinline__ float fast_atan01(float x) {
    float t = x * x;
    float p = -0.0117212f;
    p = fmaf(p, t,  0.05265332f);
    p = fmaf(p, t, -0.11643287f);
    p = fmaf(p, t,  0.19354346f);
    p = fmaf(p, t, -0.33262347f);
    p = fmaf(p, t,  0.99997726f);
    return x * p;
}

// sum of Huber(phi_i/HUBER) for phi = so3_log of quat q (branch-free).
__device__ __forceinline__ float huber3_qlog(const float q[4]) {
    float w = q[0], x = q[1], y = q[2], z = q[3];
    float sg = (w < 0.0f) ? -1.0f : 1.0f;
    w *= sg; x *= sg; y *= sg; z *= sg;
    float nv2 = x*x + y*y + z*z;
    float nv = nv2 * __frsqrt_rn(fmaxf(nv2, 1e-24f));
    float lo = fminf(nv, w), hi = fmaxf(nv, w);
    float at = fast_atan01(__fdividef(lo, hi));
    float th = 2.0f * ((nv <= w) ? at : (1.57079632679f - at));
    float f = __fdividef(th, fmaxf(nv, 1e-20f)) * (1.0f / HUBER_F);
    float acc = 0.0f;
#pragma unroll
    for (int t = 0; t < 3; t++) {
        float zz = f * ((t == 0) ? x : (t == 1) ? y : z);
        float az = fabsf(zz);
        acc += (az < 1.0f) ? (0.5f * zz * zz) : (az - 0.5f);
    }
    return acc;
}

// BCH suffix-scan step (reverse time order): C += w x S; S += w
__device__ __forceinline__ void bch_step(float wx, float wy, float wz,
                                         float S[3], float C[3]) {
    C[0] = fmaf(wy, S[2], fmaf(-wz, S[1], C[0]));
    C[1] = fmaf(wz, S[0], fmaf(-wx, S[2], C[1]));
    C[2] = fmaf(wx, S[1], fmaf(-wy, S[0], C[2]));
    S[0] += wx; S[1] += wy; S[2] += wz;
}

// merge A(earlier) ⊕ B(later): S = Sa+Sb, C = Ca+Cb + Sa x Sb
__device__ __forceinline__ void bch_merge(const float Sa[3], const float Ca[3],
                                          const float Sb[3], const float Cb[3],
                                          float S[3], float C[3]) {
    S[0] = Sa[0] + Sb[0];
    S[1] = Sa[1] + Sb[1];
    S[2] = Sa[2] + Sb[2];
    C[0] = Ca[0] + Cb[0] + (Sa[1]*Sb[2] - Sa[2]*Sb[1]);
    C[1] = Ca[1] + Cb[1] + (Sa[2]*Sb[0] - Sa[0]*Sb[2]);
    C[2] = Ca[2] + Cb[2] + (Sa[0]*Sb[1] - Sa[1]*Sb[0]);
}

// shuffle (S,C) down by d
__device__ __forceinline__ void shfl_sc(const float S[3], const float C[3], int d,
                                        float So[3], float Co[3]) {
#pragma unroll
    for (int k = 0; k < 3; k++) {
        So[k] = __shfl_down_sync(0xFFFFFFFFu, S[k], d);
        Co[k] = __shfl_down_sync(0xFFFFFFFFu, C[k], d);
    }
}

__global__ void __launch_bounds__(TPB, 6)
gyro_main_kernel(const float* __restrict__ xs, const float* __restrict__ hx,
                 float* __restrict__ out, int cnt4, int cnt5) {
    int t = blockIdx.x * TPB + threadIdx.x;          // quarter-group (4 incr)
    int m = t & 3;
    int g = t >> 2;                                  // 16-group index

    // --- loads: thread t owns float4 indices 3t..3t+2; xs broadcast per quad ---
    const float4* hp = reinterpret_cast<const float4*>(hx) + (size_t)t * 3;
    float4 f0 = hp[0], f1 = hp[1], f2 = hp[2];
    float4 xv = *reinterpret_cast<const float4*>(xs + (size_t)g * 48);

    // --- BCH-4 scan over own 4 increments (reverse time order) ---
    float S[3], C[3];
    S[0] = f2.y; S[1] = f2.z; S[2] = f2.w;           // incr 3
    C[0] = 0.0f; C[1] = 0.0f; C[2] = 0.0f;
    bch_step(f1.z, f1.w, f2.x, S, C);                // incr 2
    bch_step(f0.w, f1.x, f1.y, S, C);                // incr 1
    bch_step(f0.x, f0.y, f0.z, S, C);                // incr 0

    // --- stage A: merge with next lane (valid on even m) ---
    float Sn[3], Cn[3], S8[3], C8[3];
    shfl_sc(S, C, 1, Sn, Cn);
    bch_merge(S, C, Sn, Cn, S8, C8);

    // --- stage B: merge with lane+2's stage-A (full 16-group on m==0) ---
    float S16[3], C16[3];
    shfl_sc(S8, C8, 2, Sn, Cn);
    bch_merge(S8, C8, Sn, Cn, S16, C16);

    // --- own-group quaternion + ground truth ---
    const float H2 = 0.5f * DT_F * DT_F;
    float q16[4];
    qexp_phi_small(fmaf(H2, C16[0], DT_F * S16[0]),
                   fmaf(H2, C16[1], DT_F * S16[1]),
                   fmaf(H2, C16[2], DT_F * S16[2]), q16);
    float qR[4];
    qexp_full(xv.x, xv.y, xv.z, qR);

    // --- level-4 relative rotation (valid on m==0) ---
    float rel4[4];
    qcmul(q16, qR, rel4);

    // --- level-5: merge with group at lane+4 (valid data on lanes ≡0 mod 8) ---
    float S32[3], C32[3];
    shfl_sc(S16, C16, 4, Sn, Cn);
    bch_merge(S16, C16, Sn, Cn, S32, C32);
    float q32[4];
    qexp_phi_small(fmaf(H2, C32[0], DT_F * S32[0]),
                   fmaf(H2, C32[1], DT_F * S32[1]),
                   fmaf(H2, C32[2], DT_F * S32[2]), q32);
    float rB[4];
#pragma unroll
    for (int k = 0; k < 4; k++)
        rB[k] = __shfl_down_sync(0xFFFFFFFFu, qR[k], 4);
    float r32[4], rel5[4];
    qmul(qR, rB, r32);
    qcmul(q32, r32, rel5);
    // route rel5 from lane m==0 to lane m==1
    float rel5r[4];
#pragma unroll
    for (int k = 0; k < 4; k++)
        rel5r[k] = __shfl_up_sync(0xFFFFFFFFu, rel5[k], 1);

    // --- single converged log/huber ---
    float rel[4];
#pragma unroll
    for (int k = 0; k < 4; k++) rel[k] = (m == 1) ? rel5r[k] : rel4[k];
    float h = huber3_qlog(rel);

    float s4 = 0.0f, s5 = 0.0f;
    if (m == 0) {
        int i4 = g & (NPER4 - 1);
        if (i4 >= N0) s4 = h;
    } else if (m == 1 && ((g & 1) == 0)) {           // source lane was ≡0 mod 8
        int j5 = (g >> 1) & (NPER5 - 1);
        if (j5 >= N0) s5 = h;
    }

    // --- reduction ---
#pragma unroll
    for (int off = 16; off > 0; off >>= 1) {
        s4 += __shfl_down_sync(0xFFFFFFFFu, s4, off);
        s5 += __shfl_down_sync(0xFFFFFFFFu, s5, off);
    }
    __shared__ float sh4[TPB / 32];
    __shared__ float sh5[TPB / 32];
    int lane = threadIdx.x & 31;
    int warp = threadIdx.x >> 5;
    if (lane == 0) { sh4[warp] = s4; sh5[warp] = s5; }
    __syncthreads();

    if (threadIdx.x == 0) {
        float b4 = 0.0f, b5 = 0.0f;
#pragma unroll
        for (int w = 0; w < TPB / 32; w++) { b4 += sh4[w]; b5 += sh5[w]; }
        atomicAdd(&g_sum4, (double)b4);
        atomicAdd(&g_sum5, (double)b5);
        __threadfence();
        unsigned int ticket = atomicAdd(&g_count, 1u);
        if (ticket == gridDim.x - 1) {
            double s4t = atomicAdd(&g_sum4, 0.0);
            double s5t = atomicAdd(&g_sum5, 0.0);
            // loss = W*HUBER^2 * (mean4 + 0.5*mean5); W*HUBER^2 = 25
            double loss = 25.0 * (s4t / (double)cnt4 + 0.5 * s5t / (double)cnt5);
            out[0] = (float)loss;
            g_sum4 = 0.0;
            g_sum5 = 0.0;
            __threadfence();
            g_count = 0u;
        }
    }
}

extern "C" void kernel_launch(void* const* d_in, const int* in_sizes, int n_in,
                              void* d_out, int out_size) {
    const float* xs = (const float*)d_in[0];
    // d_in[1] = dp, unused by forward
    const float* hx = (const float*)d_in[2];

    int total = in_sizes[2];              // N*T*3 = 6291456
    int quads = total / 12;               // 524288 threads (4 increments each)
    int groups = total / 48;              // 131072
    int nbatch = 64;
    int g4_per_batch = groups / nbatch;   // 2048
    int g5_per_batch = g4_per_batch / 2;  // 1024
    int cnt4 = nbatch * (g4_per_batch - N0) * 3;   // 392256
    int cnt5 = nbatch * (g5_per_batch - N0) * 3;   // 195648

    gyro_main_kernel<<<quads / TPB, TPB>>>(xs, hx, (float*)d_out, cnt4, cnt5);
}

// round 13
// speedup vs baseline: 1.1775x; 1.1775x over previous
#include <cuda_runtime.h>

// GyroLoss forward — R10 (BCH-8 + quat epilogue, 262144 threads) with
// 256-bit LDG.E.256 loads (ld.global.nc.v4.u64). Schedule, math, and
// reduction identical to R10 (best-known).

#define DT_F 0.01f
#define HUBER_F 0.005f
#define NPER4 2048
#define NPER5 1024
#define N0 5
#define TPB 256

typedef unsigned long long u64t;

__device__ double g_sum4 = 0.0;
__device__ double g_sum5 = 0.0;
__device__ unsigned int g_count = 0u;

__device__ __forceinline__ void qmul(const float a[4], const float b[4], float c[4]) {
    c[0] = a[0]*b[0] - a[1]*b[1] - a[2]*b[2] - a[3]*b[3];
    c[1] = a[0]*b[1] + a[1]*b[0] + a[2]*b[3] - a[3]*b[2];
    c[2] = a[0]*b[2] - a[1]*b[3] + a[2]*b[0] + a[3]*b[1];
    c[3] = a[0]*b[3] + a[1]*b[2] - a[2]*b[1] + a[3]*b[0];
}

// c = conj(a) ⊗ b
__device__ __forceinline__ void qcmul(const float a[4], const float b[4], float c[4]) {
    c[0] = a[0]*b[0] + a[1]*b[1] + a[2]*b[2] + a[3]*b[3];
    c[1] = a[0]*b[1] - a[1]*b[0] - a[2]*b[3] + a[3]*b[2];
    c[2] = a[0]*b[2] + a[1]*b[3] - a[2]*b[0] - a[3]*b[1];
    c[3] = a[0]*b[3] - a[1]*b[2] + a[2]*b[1] - a[3]*b[0];
}

__device__ __forceinline__ void qexp_phi_small(float x, float y, float z, float q[4]) {
    float sq = x*x + y*y + z*z;
    float hq = 0.25f * sq;
    q[0] = 1.0f + hq * (-0.5f + hq * (1.0f / 24.0f));
    float sf = 0.5f * (1.0f + hq * (-(1.0f / 6.0f) + hq * (1.0f / 120.0f)));
    q[1] = sf * x; q[2] = sf * y; q[3] = sf * z;
}

__device__ __forceinline__ void qexp_full(float x, float y, float z, float q[4]) {
    float sq = x*x + y*y + z*z;
    float a = sq * __frsqrt_rn(fmaxf(sq, 1e-16f));
    float h = 0.5f * a;
    float sh = __sinf(h), ch = __cosf(h);
    float sf = __fdividef(sh, fmaxf(a, 1e-8f));
    q[0] = ch; q[1] = sf * x; q[2] = sf * y; q[3] = sf * z;
}

__device__ __forceinline__ float fast_atan01(float x) {
    float t = x * x;
    float p = -0.0117212f;
    p = fmaf(p, t,  0.05265332f);
    p = fmaf(p, t, -0.11643287f);
    p = fmaf(p, t,  0.19354346f);
    p = fmaf(p, t, -0.33262347f);
    p = fmaf(p, t,  0.99997726f);
    return x * p;
}

__device__ __forceinline__ float huber3_qlog(const float q[4]) {
    float w = q[0], x = q[1], y = q[2], z = q[3];
    float sg = (w < 0.0f) ? -1.0f : 1.0f;
    w *= sg; x *= sg; y *= sg; z *= sg;
    float nv2 = x*x + y*y + z*z;
    float nv = nv2 * __frsqrt_rn(fmaxf(nv2, 1e-24f));
    float lo = fminf(nv, w), hi = fmaxf(nv, w);
    float at = fast_atan01(__fdividef(lo, hi));
    float th = 2.0f * ((nv <= w) ? at : (1.57079632679f - at));
    float f = __fdividef(th, fmaxf(nv, 1e-20f)) * (1.0f / HUBER_F);
    float acc = 0.0f;
#pragma unroll
    for (int t = 0; t < 3; t++) {
        float zz = f * ((t == 0) ? x : (t == 1) ? y : z);
        float az = fabsf(zz);
        acc += (az < 1.0f) ? (0.5f * zz * zz) : (az - 0.5f);
    }
    return acc;
}

// BCH suffix-scan step (reverse time order): C += w x S; S += w
__device__ __forceinline__ void bch_step(float wx, float wy, float wz,
                                         float S[3], float C[3]) {
    C[0] = fmaf(wy, S[2], fmaf(-wz, S[1], C[0]));
    C[1] = fmaf(wz, S[0], fmaf(-wx, S[2], C[1]));
    C[2] = fmaf(wx, S[1], fmaf(-wy, S[0], C[2]));
    S[0] += wx; S[1] += wy; S[2] += wz;
}

// 256-bit non-coherent global load
__device__ __forceinline__ void ldg256(const void* p, u64t r[4]) {
    asm("ld.global.nc.v4.u64 {%0,%1,%2,%3}, [%4];"
        : "=l"(r[0]), "=l"(r[1]), "=l"(r[2]), "=l"(r[3]) : "l"(p));
}
__device__ __forceinline__ void u2f(u64t u, float& a, float& b) {
    a = __uint_as_float((unsigned)u);
    b = __uint_as_float((unsigned)(u >> 32));
}

__global__ void __launch_bounds__(TPB)
gyro_main_kernel(const float* __restrict__ xs, const float* __restrict__ hx,
                 float* __restrict__ out, int cnt4, int cnt5) {
    int t = blockIdx.x * TPB + threadIdx.x;   // half-group (8 increments)
    int lane = threadIdx.x & 31;

    // --- 24 floats via 3x LDG.256 (96B per thread, 32B-aligned) + xs ---
    const char* base = reinterpret_cast<const char*>(hx) + (size_t)t * 96;
    u64t A[4], B[4], Cld[4];
    ldg256(base, A);
    ldg256(base + 32, B);
    ldg256(base + 64, Cld);
    float4 xv = __ldg(reinterpret_cast<const float4*>(xs + (size_t)(t >> 1) * 48));

    float v[24];
    u2f(A[0],  v[0],  v[1]);  u2f(A[1],  v[2],  v[3]);
    u2f(A[2],  v[4],  v[5]);  u2f(A[3],  v[6],  v[7]);
    u2f(B[0],  v[8],  v[9]);  u2f(B[1],  v[10], v[11]);
    u2f(B[2],  v[12], v[13]); u2f(B[3],  v[14], v[15]);
    u2f(Cld[0], v[16], v[17]); u2f(Cld[1], v[18], v[19]);
    u2f(Cld[2], v[20], v[21]); u2f(Cld[3], v[22], v[23]);

    // --- BCH-2 suffix scan over 8 raw increments (reverse time order) ---
    float S[3] = {0.0f, 0.0f, 0.0f};
    float C[3] = {0.0f, 0.0f, 0.0f};
    bch_step(v[21], v[22], v[23], S, C);   // incr 7
    bch_step(v[18], v[19], v[20], S, C);   // incr 6
    bch_step(v[15], v[16], v[17], S, C);   // incr 5
    bch_step(v[12], v[13], v[14], S, C);   // incr 4
    bch_step(v[9],  v[10], v[11], S, C);   // incr 3
    bch_step(v[6],  v[7],  v[8],  S, C);   // incr 2
    bch_step(v[3],  v[4],  v[5],  S, C);   // incr 1
    bch_step(v[0],  v[1],  v[2],  S, C);   // incr 0
    float px = fmaf(0.5f * DT_F * DT_F, C[0], DT_F * S[0]);
    float py = fmaf(0.5f * DT_F * DT_F, C[1], DT_F * S[1]);
    float pz = fmaf(0.5f * DT_F * DT_F, C[2], DT_F * S[2]);
    float q8[4];
    qexp_phi_small(px, py, pz, q8);

    // --- 16-group: even lane combines with odd partner ---
    float q16[4];
    {
        float qp[4];
#pragma unroll
        for (int k = 0; k < 4; k++)
            qp[k] = __shfl_down_sync(0xFFFFFFFFu, q8[k], 1);
        qmul(q8, qp, q16);                           // valid on even lanes
    }

    // --- ground-truth quat (pair lanes broadcast same float4) ---
    float qR[4];
    qexp_full(xv.x, xv.y, xv.z, qR);

    // --- level-5 operands: gather within lane quad ---
    int lb = lane & ~3;
    float q32[4], qR32[4];
    {
        float qa[4], qb[4], ra[4];
#pragma unroll
        for (int k = 0; k < 4; k++) {
            qa[k] = __shfl_sync(0xFFFFFFFFu, q16[k], lb);
            qb[k] = __shfl_sync(0xFFFFFFFFu, q16[k], lb | 2);
            ra[k] = __shfl_sync(0xFFFFFFFFu, qR[k],  lb);
        }
        qmul(qa, qb, q32);                           // used on lane ≡3
        qmul(ra, qR, qR32);                          // lane3's own qR = group 2j+1
    }

    // --- converged relative-rotation log + huber ---
    int m = t & 3;
    float relA[4], relB[4], rel[4];
    qcmul(q16, qR, relA);                            // level-4 (even lanes)
    qcmul(q32, qR32, relB);                          // level-5 (lane ≡3)
#pragma unroll
    for (int k = 0; k < 4; k++) rel[k] = (m == 3) ? relB[k] : relA[k];
    float h = huber3_qlog(rel);

    float s4 = 0.0f, s5 = 0.0f;
    if ((m & 1) == 0) {                              // lanes ≡0,2: level-4
        int i4 = (t >> 1) & (NPER4 - 1);
        if (i4 >= N0) s4 = h;
    } else if (m == 3) {                             // lane ≡3: level-5
        int j5 = (t >> 2) & (NPER5 - 1);
        if (j5 >= N0) s5 = h;
    }

    // --- reduction ---
#pragma unroll
    for (int off = 16; off > 0; off >>= 1) {
        s4 += __shfl_down_sync(0xFFFFFFFFu, s4, off);
        s5 += __shfl_down_sync(0xFFFFFFFFu, s5, off);
    }
    __shared__ float sh4[TPB / 32];
    __shared__ float sh5[TPB / 32];
    int warp = threadIdx.x >> 5;
    if (lane == 0) { sh4[warp] = s4; sh5[warp] = s5; }
    __syncthreads();

    if (threadIdx.x == 0) {
        float b4 = 0.0f, b5 = 0.0f;
#pragma unroll
        for (int w = 0; w < TPB / 32; w++) { b4 += sh4[w]; b5 += sh5[w]; }
        atomicAdd(&g_sum4, (double)b4);
        atomicAdd(&g_sum5, (double)b5);
        __threadfence();
        unsigned int ticket = atomicAdd(&g_count, 1u);
        if (ticket == gridDim.x - 1) {
            double s4t = atomicAdd(&g_sum4, 0.0);
            double s5t = atomicAdd(&g_sum5, 0.0);
            // loss = W*HUBER^2 * (mean4 + 0.5*mean5); W*HUBER^2 = 25
            double loss = 25.0 * (s4t / (double)cnt4 + 0.5 * s5t / (double)cnt5);
            out[0] = (float)loss;
            g_sum4 = 0.0;
            g_sum5 = 0.0;
            __threadfence();
            g_count = 0u;
        }
    }
}

extern "C" void kernel_launch(void* const* d_in, const int* in_sizes, int n_in,
                              void* d_out, int out_size) {
    const float* xs = (const float*)d_in[0];
    // d_in[1] = dp, unused by forward
    const float* hx = (const float*)d_in[2];

    int total = in_sizes[2];              // N*T*3 = 6291456
    int halves = total / 24;              // 262144 threads (8 increments each)
    int groups = total / 48;              // 131072
    int nbatch = 64;
    int g4_per_batch = groups / nbatch;   // 2048
    int g5_per_batch = g4_per_batch / 2;  // 1024
    int cnt4 = nbatch * (g4_per_batch - N0) * 3;   // 392256
    int cnt5 = nbatch * (g5_per_batch - N0) * 3;   // 195648

    gyro_main_kernel<<<halves / TPB, TPB>>>(xs, hx, (float*)d_out, cnt4, cnt5);
}